// round 3
// baseline (speedup 1.0000x reference)
#include <cuda_runtime.h>
#include <cuda_fp16.h>
#include <cuda_bf16.h>
#include <cstdint>

#define T_DIM   64
#define IN_DIM  4100
#define OUT_DIM 12288
#define G_DIM   820
#define KCB     256
#define GRP     5
#define KPAD    4160          // 52 chunks * 80
#define NCHUNK  52
#define GPC     16            // groups per chunk
#define KC      80            // k elements per chunk

// ---------------- device globals (scratch; no allocations allowed) ----------
__device__ unsigned g_xmax_bits;
__device__ unsigned g_cbmax_bits;
__device__ int      g_cb_dtype;                       // 0=f16 1=bf16 2=f32
__device__ __align__(16) __half g_cbtab[2 * KCB * 8]; // canonical normalized codebooks
__device__ __half   g_xsafe[T_DIM * KPAD];            // 532 KB fp16 x, zero-padded

// ---------------- small helper kernels ----------------
__global__ void k_init() { g_xmax_bits = 0u; g_cbmax_bits = 0u; g_cb_dtype = 0; }

__device__ __forceinline__ float block_max_256(float m) {
    #pragma unroll
    for (int o = 16; o; o >>= 1) m = fmaxf(m, __shfl_xor_sync(0xffffffffu, m, o));
    __shared__ float sm[8];
    int lane = threadIdx.x & 31, w = threadIdx.x >> 5;
    if (!lane) sm[w] = m;
    __syncthreads();
    if (!w) {
        m = (lane < 8) ? sm[lane] : 0.f;
        #pragma unroll
        for (int o = 4; o; o >>= 1) m = fmaxf(m, __shfl_xor_sync(0xffffffffu, m, o));
    }
    return m;
}

// ---- dtype detector: reads only first 5120 bytes (min possible buffer) ----
__global__ void k_detect(const void* __restrict__ cbraw) {
    const __half*         h = (const __half*)cbraw;
    const __nv_bfloat16*  b = (const __nv_bfloat16*)cbraw;
    float mh = 0.f, mb = 0.f;
    for (int i = threadIdx.x; i < 2 * KCB * GRP; i += 256) {
        mh = fmaxf(mh, fabsf(__half2float(h[i])));
        mb = fmaxf(mb, fabsf(__bfloat162float(b[i])));
    }
    __shared__ float smh[8], smb[8];
    int lane = threadIdx.x & 31, w = threadIdx.x >> 5;
    #pragma unroll
    for (int o = 16; o; o >>= 1) {
        mh = fmaxf(mh, __shfl_xor_sync(0xffffffffu, mh, o));
        mb = fmaxf(mb, __shfl_xor_sync(0xffffffffu, mb, o));
    }
    if (!lane) { smh[w] = mh; smb[w] = mb; }
    __syncthreads();
    if (threadIdx.x == 0) {
        float MH = 0.f, MB = 0.f;
        #pragma unroll
        for (int i = 0; i < 8; ++i) { MH = fmaxf(MH, smh[i]); MB = fmaxf(MB, smb[i]); }
        g_cb_dtype = (MH <= 1.0f) ? 0 : ((MB <= 1.0f) ? 1 : 2);
    }
}

// ---- build canonical codebook table (normalized, padded to 8 halves) ----
__global__ void k_cb_prep(const void* __restrict__ cbraw) {
    const int dt = g_cb_dtype;
    const __half*        h  = (const __half*)cbraw;
    const __nv_bfloat16* bf = (const __nv_bfloat16*)cbraw;
    const float*         f  = (const float*)cbraw;
    const int N = 2 * KCB * GRP;

    float m = 0.f;
    for (int i = threadIdx.x; i < N; i += 256) {
        float v = (dt == 0) ? __half2float(h[i])
                : (dt == 1) ? __bfloat162float(bf[i])
                            : f[i];
        m = fmaxf(m, fabsf(v));
    }
    m = block_max_256(m);
    __shared__ float s_cbm;
    if (threadIdx.x == 0) {
        g_cbmax_bits = __float_as_uint(m);
        s_cbm = fmaxf(m, 1.0f);
    }
    __syncthreads();
    const float cbm = s_cbm;

    for (int e = threadIdx.x; e < 2 * KCB; e += 256) {
        #pragma unroll
        for (int j = 0; j < 5; ++j) {
            int i = e * GRP + j;
            float v = (dt == 0) ? __half2float(h[i])
                    : (dt == 1) ? __bfloat162float(bf[i])
                                : f[i];
            g_cbtab[e * 8 + j] = __float2half(v / cbm);
        }
        #pragma unroll
        for (int j = 5; j < 8; ++j) g_cbtab[e * 8 + j] = __float2half(0.0f);
    }
}

__global__ void k_absmax_x(const float* __restrict__ x, int n) {
    float m = 0.f;
    for (int i = blockIdx.x * blockDim.x + threadIdx.x; i < n; i += gridDim.x * blockDim.x)
        m = fmaxf(m, fabsf(x[i]));
    m = block_max_256(m);
    if (threadIdx.x == 0) atomicMax(&g_xmax_bits, __float_as_uint(m));
}

__global__ void k_convert(const float* __restrict__ x) {
    float xm = fmaxf(__uint_as_float(g_xmax_bits), 1.0f) * 8.0f;
    int i = blockIdx.x * blockDim.x + threadIdx.x;
    if (i >= T_DIM * KPAD) return;
    int t = i / KPAD, c = i - t * KPAD;
    __half v = __float2half(0.0f);
    if (c < IN_DIM) v = __float2half(x[t * IN_DIM + c] / xm);
    g_xsafe[i] = v;
}

// ---------------- PTX helpers ----------------
__device__ __forceinline__ uint32_t hadd2u(uint32_t a, uint32_t b) {
    uint32_t r;
    asm("add.rn.f16x2 %0, %1, %2;" : "=r"(r) : "r"(a), "r"(b));
    return r;
}

__device__ __forceinline__ void ldmx4(uint32_t& r0, uint32_t& r1, uint32_t& r2, uint32_t& r3,
                                      uint32_t addr) {
    asm volatile("ldmatrix.sync.aligned.m8n8.x4.shared.b16 {%0,%1,%2,%3}, [%4];\n"
                 : "=r"(r0), "=r"(r1), "=r"(r2), "=r"(r3) : "r"(addr));
}

__device__ __forceinline__ void mma16816(float* d, const uint32_t* a, uint32_t b0, uint32_t b1) {
    asm volatile("mma.sync.aligned.m16n8k16.row.col.f32.f16.f16.f32 "
                 "{%0,%1,%2,%3},{%4,%5,%6,%7},{%8,%9},{%0,%1,%2,%3};\n"
                 : "+f"(d[0]), "+f"(d[1]), "+f"(d[2]), "+f"(d[3])
                 : "r"(a[0]), "r"(a[1]), "r"(a[2]), "r"(a[3]), "r"(b0), "r"(b1));
}

// nan/inf -> 0 that survives fast-math: exponent-bits test
__device__ __forceinline__ float finite_or_zero(float v) {
    unsigned b = __float_as_uint(v);
    return ((b & 0x7F800000u) == 0x7F800000u) ? 0.f : v;
}

// ---------------- main fused decode + GEMM kernel ----------------
// CTA: 64 t (all) x 64 o.  8 warps = 4(m) x 2(n); each warp: m16 x n32.
// W tile smem: 64 rows x 88 halves (176B stride -> conflict-free ldmatrix).
#define WROW 88

__device__ __forceinline__ void store_group(__half* wbuf, int ol, int gl,
                                            uint32_t u0, uint32_t u1, uint32_t u2) {
    char* p = reinterpret_cast<char*>(wbuf + ol * WROW) + gl * 10;
    if (gl & 1) {                         // byte offset == 2 (mod 4)
        *reinterpret_cast<unsigned short*>(p)     = (unsigned short)(u0 & 0xFFFFu);
        *reinterpret_cast<uint32_t*>(p + 2)       = (u0 >> 16) | (u1 << 16);
        *reinterpret_cast<uint32_t*>(p + 6)       = (u1 >> 16) | (u2 << 16);
    } else {                              // 4B aligned
        *reinterpret_cast<uint32_t*>(p)           = u0;
        *reinterpret_cast<uint32_t*>(p + 4)       = u1;
        *reinterpret_cast<unsigned short*>(p + 8) = (unsigned short)(u2 & 0xFFFFu);
    }
}

__device__ __forceinline__ void load_idx(int2* pidx, const int2* __restrict__ idx2,
                                         int o0, int gbase, int tid) {
    #pragma unroll
    for (int p = 0; p < 4; ++p) {
        int linear = p * 256 + tid;
        int ol = linear >> 4, gl = linear & 15;
        int gg = gbase + gl;
        pidx[p] = (gg < G_DIM) ? idx2[(o0 + ol) * G_DIM + gg] : make_int2(0, 0);
    }
}

__device__ __forceinline__ void decode_chunk(__half* wbuf, const int2* pidx, int gbase,
                                             const uint4* __restrict__ cbt, int tid) {
    #pragma unroll
    for (int p = 0; p < 4; ++p) {
        int linear = p * 256 + tid;
        int ol = linear >> 4, gl = linear & 15;
        int gg = gbase + gl;
        uint32_t u0 = 0, u1 = 0, u2 = 0;
        if (gg < G_DIM) {
            uint4 a = cbt[pidx[p].x & 0xFF];          // mask: OOB impossible
            uint4 b = cbt[256 + (pidx[p].y & 0xFF)];
            u0 = hadd2u(a.x, b.x);
            u1 = hadd2u(a.y, b.y);
            u2 = hadd2u(a.z, b.z);
        }
        store_group(wbuf, ol, gl, u0, u1, u2);
    }
}

__global__ void __launch_bounds__(256, 2)
k_gemm(const int* __restrict__ idx,
       const float* __restrict__ scales, float* __restrict__ out) {
    __shared__ __align__(16) __half s_cb[2 * KCB * 8];      // 8 KB padded codebooks
    __shared__ __align__(16) __half s_w[2][T_DIM * WROW];   // 2 x 11 KB W tiles

    const int tid  = threadIdx.x;
    const int lane = tid & 31;
    const int wid  = tid >> 5;
    const int wm   = wid & 3;          // m warp (0..3)
    const int wn   = wid >> 2;         // n warp (0..1)
    const int m0   = wm * 16;
    const int nb   = wn * 32;
    const int o0   = blockIdx.x * 64;

    const float xm  = fmaxf(__uint_as_float(g_xmax_bits), 1.0f) * 8.0f;
    const float cbm = fmaxf(__uint_as_float(g_cbmax_bits), 1.0f);

    // --- stage canonical codebooks into smem (uint4 copies) ---
    {
        const uint4* src = reinterpret_cast<const uint4*>(g_cbtab);
        uint4* dst = reinterpret_cast<uint4*>(s_cb);
        #pragma unroll
        for (int i = tid; i < 2 * KCB; i += 256) dst[i] = src[i];
    }
    const uint4* cbt = reinterpret_cast<const uint4*>(s_cb);
    const int2* idx2 = reinterpret_cast<const int2*>(idx);

    float acc[4][4];
    #pragma unroll
    for (int i = 0; i < 4; ++i)
        #pragma unroll
        for (int j = 0; j < 4; ++j) acc[i][j] = 0.f;

    // --- prologue: decode chunk 0 ---
    int2 pA[4], pB[4];
    #pragma unroll
    for (int p = 0; p < 4; ++p) pB[p] = make_int2(0, 0);
    load_idx(pA, idx2, o0, 0, tid);
    __syncthreads();                           // codebooks ready
    decode_chunk(&s_w[0][0], pA, 0, cbt, tid);
    load_idx(pA, idx2, o0, GPC, tid);          // chunk 1 indices
    __syncthreads();                           // s_w[0] ready

    const int arow = m0 + (lane >> 2);
    const __half* xp  = g_xsafe + arow * KPAD;
    const __half* xp8 = xp + 8 * KPAD;

    for (int c = 0; c < NCHUNK; ++c) {
        if (c + 2 < NCHUNK) load_idx(pB, idx2, o0, (c + 2) * GPC, tid);

        // A fragments for all 5 k-steps (batched LDG for MLP)
        uint32_t A[5][4];
        const int kb = c * KC + ((lane & 3) << 1);
        #pragma unroll
        for (int ks = 0; ks < 5; ++ks) {
            int kk = kb + ks * 16;
            A[ks][0] = *reinterpret_cast<const uint32_t*>(xp  + kk);
            A[ks][1] = *reinterpret_cast<const uint32_t*>(xp8 + kk);
            A[ks][2] = *reinterpret_cast<const uint32_t*>(xp  + kk + 8);
            A[ks][3] = *reinterpret_cast<const uint32_t*>(xp8 + kk + 8);
        }

        uint32_t swb = (uint32_t)__cvta_generic_to_shared(&s_w[c & 1][0]);
        const int grp = lane >> 3, rin = lane & 7;
        #pragma unroll
        for (int ks = 0; ks < 5; ++ks) {
            #pragma unroll
            for (int pr = 0; pr < 2; ++pr) {
                int nrow = nb + pr * 16 + ((grp >> 1) << 3) + rin;
                uint32_t addr = swb + nrow * (WROW * 2) + ks * 32 + ((grp & 1) << 4);
                uint32_t b0, b1, b2, b3;
                ldmx4(b0, b1, b2, b3, addr);
                mma16816(acc[pr * 2],     A[ks], b0, b1);
                mma16816(acc[pr * 2 + 1], A[ks], b2, b3);
            }
        }

        if (c + 1 < NCHUNK)
            decode_chunk(&s_w[(c + 1) & 1][0], pA, (c + 1) * GPC, cbt, tid);
        #pragma unroll
        for (int p = 0; p < 4; ++p) pA[p] = pB[p];
        __syncthreads();
    }

    // --- epilogue: scale, nan_to_num, store ---
    const float xmcb = xm * cbm;
    #pragma unroll
    for (int nt = 0; nt < 4; ++nt) {
        int col = o0 + nb + nt * 8 + ((lane & 3) << 1);
        int row = m0 + (lane >> 2);
        float s0 = scales[col]     * xmcb;
        float s1 = scales[col + 1] * xmcb;
        float v0 = finite_or_zero(acc[nt][0] * s0);
        float v1 = finite_or_zero(acc[nt][1] * s1);
        float v2 = finite_or_zero(acc[nt][2] * s0);
        float v3 = finite_or_zero(acc[nt][3] * s1);
        *reinterpret_cast<float2*>(&out[(size_t)row * OUT_DIM + col])       = make_float2(v0, v1);
        *reinterpret_cast<float2*>(&out[(size_t)(row + 8) * OUT_DIM + col]) = make_float2(v2, v3);
    }
}

// ---------------- launcher ----------------
extern "C" void kernel_launch(void* const* d_in, const int* in_sizes, int n_in,
                              void* d_out, int out_size) {
    // Inputs identified by unique element counts:
    //   x: 262400 (f32), indices: 20152320 (i32), codebooks: 2560 (fp ambiguous), scales: 12288 (f32)
    const float* x       = nullptr;
    const int*   indices = nullptr;
    const void*  cbooks  = nullptr;
    const float* scales  = nullptr;
    for (int i = 0; i < n_in; ++i) {
        switch (in_sizes[i]) {
            case T_DIM * IN_DIM:      x       = (const float*)d_in[i]; break;
            case OUT_DIM * G_DIM * 2: indices = (const int*)d_in[i];   break;
            case 2 * KCB * GRP:       cbooks  = d_in[i];               break;
            case OUT_DIM:             scales  = (const float*)d_in[i]; break;
        }
    }
    float* out = (float*)d_out;

    k_init<<<1, 1>>>();
    k_detect<<<1, 256>>>(cbooks);
    k_cb_prep<<<1, 256>>>(cbooks);
    k_absmax_x<<<128, 256>>>(x, T_DIM * IN_DIM);
    k_convert<<<(T_DIM * KPAD + 255) / 256, 256>>>(x);
    k_gemm<<<OUT_DIM / 64, 256>>>(indices, scales, out);
}